// round 1
// baseline (speedup 1.0000x reference)
#include <cuda_runtime.h>
#include <math.h>

#define NN    32
#define BSZv  512
#define NE    7
#define DIN   512
#define DHv   256
#define RHv   64
#define NPAIR 21
#define M_ROWS (NN * BSZv * NE)   // 114688
#define NCFG  128                 // 2^7

// ---------------- scratch (device globals; no allocation allowed) ------------
__device__ float g_h1[(size_t)M_ROWS * DHv];
__device__ float g_h2[(size_t)M_ROWS * DHv];
__device__ float g_un[(size_t)M_ROWS * 2];
__device__ float g_pairsum[(size_t)BSZv * NCFG];

// ---------------- SGEMM: C = relu(A @ B + bias), A[M,K] B[K,N] ---------------
// 128x128 tile, BK=8, 8x8 per thread, 256 threads. M%128==0, N%128==0, K%8==0.
template <int K, bool RELU>
__global__ __launch_bounds__(256) void sgemm_bias_relu(
    const float* __restrict__ A, const float* __restrict__ B,
    const float* __restrict__ bias, float* __restrict__ C, int Ncols)
{
    __shared__ float As[8][128];
    __shared__ float Bs[8][128];

    const int tid = threadIdx.x;
    const int tx = tid & 15;       // 0..15 -> column groups
    const int ty = tid >> 4;       // 0..15 -> row groups
    const int mBase = blockIdx.x * 128;
    const int nBase = blockIdx.y * 128;

    float acc[8][8];
#pragma unroll
    for (int i = 0; i < 8; i++)
#pragma unroll
        for (int j = 0; j < 8; j++) acc[i][j] = 0.f;

    const int aRow = tid >> 1;           // 0..127
    const int aCol = (tid & 1) * 4;      // 0 or 4
    const int bRow = tid >> 5;           // 0..7
    const int bCol = (tid & 31) * 4;     // 0..124

    const float* Ap = A + (size_t)(mBase + aRow) * K + aCol;
    const float* Bp = B + (size_t)bRow * Ncols + nBase + bCol;

    for (int k0 = 0; k0 < K; k0 += 8) {
        float4 a4 = *(const float4*)Ap;
        float4 b4 = *(const float4*)Bp;
        As[aCol + 0][aRow] = a4.x;
        As[aCol + 1][aRow] = a4.y;
        As[aCol + 2][aRow] = a4.z;
        As[aCol + 3][aRow] = a4.w;
        *(float4*)&Bs[bRow][bCol] = b4;
        __syncthreads();

#pragma unroll
        for (int kk = 0; kk < 8; kk++) {
            float ra[8], rb[8];
            *(float4*)(ra)     = *(const float4*)&As[kk][ty * 4];
            *(float4*)(ra + 4) = *(const float4*)&As[kk][64 + ty * 4];
            *(float4*)(rb)     = *(const float4*)&Bs[kk][tx * 4];
            *(float4*)(rb + 4) = *(const float4*)&Bs[kk][64 + tx * 4];
#pragma unroll
            for (int i = 0; i < 8; i++)
#pragma unroll
                for (int j = 0; j < 8; j++) acc[i][j] += ra[i] * rb[j];
        }
        __syncthreads();
        Ap += 8;
        Bp += (size_t)8 * Ncols;
    }

    // epilogue
    const float* bp = bias + nBase;
    float4 bA = *(const float4*)(bp + tx * 4);
    float4 bB = *(const float4*)(bp + 64 + tx * 4);
    const float bAv[4] = {bA.x, bA.y, bA.z, bA.w};
    const float bBv[4] = {bB.x, bB.y, bB.z, bB.w};

#pragma unroll
    for (int g = 0; g < 2; g++) {
#pragma unroll
        for (int r = 0; r < 4; r++) {
            int ii = g * 4 + r;
            int row = mBase + g * 64 + ty * 4 + r;
            float* Crow = C + (size_t)row * Ncols + nBase;
            float v1[4], v2[4];
#pragma unroll
            for (int j = 0; j < 4; j++) {
                float a = acc[ii][j] + bAv[j];
                float b = acc[ii][4 + j] + bBv[j];
                if (RELU) { a = fmaxf(a, 0.f); b = fmaxf(b, 0.f); }
                v1[j] = a; v2[j] = b;
            }
            *(float4*)(Crow + tx * 4)      = make_float4(v1[0], v1[1], v1[2], v1[3]);
            *(float4*)(Crow + 64 + tx * 4) = make_float4(v2[0], v2[1], v2[2], v2[3]);
        }
    }
}

// ---------------- GEMM3: un[m, 0..1] = h2[m,:] @ W2[256,2] + b2 --------------
// warp per row, 256 threads = 8 rows per block
__global__ __launch_bounds__(256) void gemm3_kernel(
    const float* __restrict__ h2, const float* __restrict__ W2,
    const float* __restrict__ b2, float* __restrict__ un)
{
    __shared__ float w[DHv * 2];
    __shared__ float bb[2];
    int tid = threadIdx.x;
    for (int i = tid; i < DHv * 2; i += 256) w[i] = W2[i];
    if (tid < 2) bb[tid] = b2[tid];
    __syncthreads();

    int warp = tid >> 5, lane = tid & 31;
    size_t row = (size_t)blockIdx.x * 8 + warp;
    const float* hrow = h2 + row * DHv;
    float4 a = *(const float4*)(hrow + lane * 4);
    float4 b = *(const float4*)(hrow + 128 + lane * 4);
    float av[4] = {a.x, a.y, a.z, a.w};
    float bv[4] = {b.x, b.y, b.z, b.w};

    float acc0 = 0.f, acc1 = 0.f;
#pragma unroll
    for (int q = 0; q < 4; q++) {
        int k0 = lane * 4 + q;
        int k1 = 128 + lane * 4 + q;
        acc0 += av[q] * w[k0 * 2 + 0];
        acc1 += av[q] * w[k0 * 2 + 1];
        acc0 += bv[q] * w[k1 * 2 + 0];
        acc1 += bv[q] * w[k1 * 2 + 1];
    }
#pragma unroll
    for (int off = 16; off; off >>= 1) {
        acc0 += __shfl_xor_sync(0xffffffffu, acc0, off);
        acc1 += __shfl_xor_sync(0xffffffffu, acc1, off);
    }
    if (lane == 0) {
        un[row * 2 + 0] = acc0 + bb[0];
        un[row * 2 + 1] = acc1 + bb[1];
    }
}

// -------- binary MLP + pairwise config sums: pairsum[b][s], 512 blocks -------
__global__ __launch_bounds__(128) void binary_kernel(
    const float* __restrict__ ctx, const float* __restrict__ R0,
    const float* __restrict__ r0, const float* __restrict__ R1,
    const float* __restrict__ r1, float* __restrict__ pairsum)
{
    __shared__ float cd[NPAIR][5];
    __shared__ float R0s[5][RHv];
    __shared__ float r0s[RHv];
    __shared__ float R1s[RHv][3];
    __shared__ float r1s[3];
    __shared__ float h2s[NPAIR][RHv];
    __shared__ float bp4s[NPAIR][4];

    int b = blockIdx.x, t = threadIdx.x;
    for (int i = t; i < NPAIR * 5; i += 128) cd[i / 5][i % 5] = ctx[b * NPAIR * 5 + i];
    for (int i = t; i < 5 * RHv; i += 128) R0s[i / RHv][i % RHv] = R0[i];
    if (t < RHv) r0s[t] = r0[t];
    for (int i = t; i < RHv * 3; i += 128) R1s[i / 3][i % 3] = R1[i];
    if (t < 3) r1s[t] = r1[t];
    __syncthreads();

    for (int idx = t; idx < NPAIR * RHv; idx += 128) {
        int p = idx / RHv, u = idx % RHv;
        float v = r0s[u];
#pragma unroll
        for (int x = 0; x < 5; x++) v += cd[p][x] * R0s[x][u];
        h2s[p][u] = fmaxf(v, 0.f);
    }
    __syncthreads();

    if (t < NPAIR * 3) {
        int p = t / 3, y = t % 3;
        float v = r1s[y];
#pragma unroll
        for (int u = 0; u < RHv; u++) v += h2s[p][u] * R1s[u][y];
        // Mmap: bp4(0,0)=bp3_0, bp4(0,1)=bp4(1,0)=bp3_1, bp4(1,1)=bp3_2
        if (y == 0) bp4s[p][0] = v;
        else if (y == 1) { bp4s[p][1] = v; bp4s[p][2] = v; }
        else bp4s[p][3] = v;
    }
    __syncthreads();

    int s = t;  // config 0..127; entity i bit = (s >> (6-i)) & 1
    float accv = 0.f;
    int p = 0;
#pragma unroll
    for (int i = 0; i < NE; i++)
#pragma unroll
        for (int j = i + 1; j < NE; j++) {
            int bi = (s >> (6 - i)) & 1;
            int bj = (s >> (6 - j)) & 1;
            accv += bp4s[p][bi * 2 + bj];
            p++;
        }
    pairsum[(size_t)b * NCFG + s] = accv;
}

// ---------------- joint + logsumexp + marginals ------------------------------
__device__ __forceinline__ float blk_sum128(float v, float* tmp, int t) {
#pragma unroll
    for (int o = 16; o; o >>= 1) v += __shfl_xor_sync(0xffffffffu, v, o);
    if ((t & 31) == 0) tmp[t >> 5] = v;
    __syncthreads();
    v = tmp[0] + tmp[1] + tmp[2] + tmp[3];
    __syncthreads();
    return v;
}
__device__ __forceinline__ float blk_max128(float v, float* tmp, int t) {
#pragma unroll
    for (int o = 16; o; o >>= 1) v = fmaxf(v, __shfl_xor_sync(0xffffffffu, v, o));
    if ((t & 31) == 0) tmp[t >> 5] = v;
    __syncthreads();
    v = fmaxf(fmaxf(tmp[0], tmp[1]), fmaxf(tmp[2], tmp[3]));
    __syncthreads();
    return v;
}

__global__ __launch_bounds__(128) void joint_kernel(
    const float* __restrict__ un, const float* __restrict__ pairsum,
    float* __restrict__ out_marg, float* __restrict__ out_joint)
{
    __shared__ float un_s[NE * 2];
    __shared__ float tmp[4];
    int b = blockIdx.x, n = blockIdx.y, s = threadIdx.x;
    size_t nb = (size_t)n * BSZv + b;
    if (s < NE * 2) un_s[s] = un[nb * (NE * 2) + s];
    __syncthreads();

    float j = pairsum[(size_t)b * NCFG + s];
#pragma unroll
    for (int i = 0; i < NE; i++) j += un_s[i * 2 + ((s >> (6 - i)) & 1)];

    float mx = blk_max128(j, tmp, s);
    float e = expf(j - mx);
    float tot = blk_sum128(e, tmp, s);
    float ltot = logf(tot);
    out_joint[nb * NCFG + s] = j - mx - ltot;

#pragma unroll
    for (int i = 0; i < NE; i++) {
        int bit = (s >> (6 - i)) & 1;
        float s1 = blk_sum128(bit ? e : 0.f, tmp, s);
        float s0 = blk_sum128(bit ? 0.f : e, tmp, s);
        if (s == i) out_marg[nb * NE + i] = logf(s1) - logf(s0);
    }
}

// ---------------- launch -----------------------------------------------------
extern "C" void kernel_launch(void* const* d_in, const int* in_sizes, int n_in,
                              void* d_out, int out_size)
{
    const float* input = (const float*)d_in[0];
    const float* ctx   = (const float*)d_in[1];
    // d_in[2] lang_input, d_in[3] num_markables: unused by reference
    const float* W0 = (const float*)d_in[4];
    const float* b0 = (const float*)d_in[5];
    const float* W1 = (const float*)d_in[6];
    const float* b1 = (const float*)d_in[7];
    const float* W2 = (const float*)d_in[8];
    const float* b2 = (const float*)d_in[9];
    const float* R0 = (const float*)d_in[10];
    const float* r0 = (const float*)d_in[11];
    const float* R1 = (const float*)d_in[12];
    const float* r1 = (const float*)d_in[13];

    float* out = (float*)d_out;
    float* out_marg = out;                    // [32,512,7]
    float* out_joint = out + (size_t)M_ROWS;  // [32,512,128]

    float *h1, *h2, *un, *ps;
    cudaGetSymbolAddress((void**)&h1, g_h1);
    cudaGetSymbolAddress((void**)&h2, g_h2);
    cudaGetSymbolAddress((void**)&un, g_un);
    cudaGetSymbolAddress((void**)&ps, g_pairsum);

    dim3 gA(M_ROWS / 128, DHv / 128);
    sgemm_bias_relu<DIN, true><<<gA, 256>>>(input, W0, b0, h1, DHv);
    sgemm_bias_relu<DHv, true><<<gA, 256>>>(h1, W1, b1, h2, DHv);
    gemm3_kernel<<<M_ROWS / 8, 256>>>(h2, W2, b2, un);
    binary_kernel<<<BSZv, 128>>>(ctx, R0, r0, R1, r1, ps);
    joint_kernel<<<dim3(BSZv, NN), 128>>>(un, ps, out_marg, out_joint);
}

// round 3
// speedup vs baseline: 2.0478x; 2.0478x over previous
#include <cuda_runtime.h>
#include <cuda_bf16.h>
#include <cstdint>
#include <math.h>

#define NN    32
#define BSZv  512
#define NE    7
#define DIN   512
#define DHv   256
#define RHv   64
#define NPAIR 21
#define M_ROWS (NN * BSZv * NE)   // 114688
#define NCFG  128

// ---------------- scratch (device globals; no allocation allowed) ------------
// packed layout: [k-chunk c][row][64 bf16 = hi(k 32) | lo(k 32)]  (128B per row)
__device__ __align__(128) __nv_bfloat16 g_w0p[(size_t)(DIN / 32) * DHv * 64];
__device__ __align__(128) __nv_bfloat16 g_w1p[(size_t)(DHv / 32) * DHv * 64];
__device__ __align__(128) __nv_bfloat16 g_h1p[(size_t)(DHv / 32) * M_ROWS * 64];
__device__ float g_un[(size_t)M_ROWS * 2];
__device__ float g_pairsum[(size_t)BSZv * NCFG];

// ---------------- PTX helpers ------------------------------------------------
__device__ __forceinline__ uint32_t smem_u32(const void* p) {
    uint32_t a;
    asm("{ .reg .u64 t; cvta.to.shared.u64 t, %1; cvt.u32.u64 %0, t; }" : "=r"(a) : "l"(p));
    return a;
}
__device__ __forceinline__ void ldsm4(uint32_t a, uint32_t* r) {
    asm volatile("ldmatrix.sync.aligned.m8n8.x4.shared.b16 {%0,%1,%2,%3}, [%4];"
                 : "=r"(r[0]), "=r"(r[1]), "=r"(r[2]), "=r"(r[3]) : "r"(a));
}
__device__ __forceinline__ void mma_bf16(float* c, const uint32_t* a, uint32_t b0, uint32_t b1) {
    asm volatile("mma.sync.aligned.m16n8k16.row.col.f32.bf16.bf16.f32 "
                 "{%0,%1,%2,%3}, {%4,%5,%6,%7}, {%8,%9}, {%0,%1,%2,%3};"
                 : "+f"(c[0]), "+f"(c[1]), "+f"(c[2]), "+f"(c[3])
                 : "r"(a[0]), "r"(a[1]), "r"(a[2]), "r"(a[3]), "r"(b0), "r"(b1));
}
#define CP16(dst, src) asm volatile("cp.async.cg.shared.global [%0], [%1], 16;" :: "r"(dst), "l"(src))
#define CPCOMMIT()     asm volatile("cp.async.commit_group;" ::: "memory")
#define CPWAIT0()      asm volatile("cp.async.wait_group 0;" ::: "memory")
#define STS128(a, v0, v1, v2, v3) \
    asm volatile("st.shared.v4.b32 [%0], {%1,%2,%3,%4};" :: "r"(a), "r"(v0), "r"(v1), "r"(v2), "r"(v3))

__device__ __forceinline__ uint32_t pack2(__nv_bfloat16 a, __nv_bfloat16 b) {
    __nv_bfloat162 t = __halves2bfloat162(a, b);
    return *reinterpret_cast<uint32_t*>(&t);
}
__device__ __forceinline__ void split2(float a, float b, uint32_t& h, uint32_t& l) {
    __nv_bfloat16 ha = __float2bfloat16_rn(a), hb = __float2bfloat16_rn(b);
    __nv_bfloat16 la = __float2bfloat16_rn(a - __bfloat162float(ha));
    __nv_bfloat16 lb = __float2bfloat16_rn(b - __bfloat162float(hb));
    h = pack2(ha, hb);
    l = pack2(la, lb);
}

// ---------------- weight packing ----------------------------------------------
// W: [K][256] fp32 row-major  ->  dst[c][n][64] bf16 (hi 32 | lo 32), c = k>>5
__global__ __launch_bounds__(256) void pack_weights(
    const float* __restrict__ W, __nv_bfloat16* __restrict__ dst, int K)
{
    int idx = blockIdx.x * 256 + threadIdx.x;
    if (idx >= K * 256) return;
    int k = idx >> 8, n = idx & 255;
    float v = W[idx];
    __nv_bfloat16 h = __float2bfloat16_rn(v);
    __nv_bfloat16 l = __float2bfloat16_rn(v - __bfloat162float(h));
    size_t o = ((size_t)(k >> 5) * 256 + n) * 64 + (k & 31);
    dst[o] = h;
    dst[o + 32] = l;
}

// ---------------- GEMM (mma.sync bf16x3) --------------------------------------
// MODE 0: A = fp32 input [M][KDIM]; out: relu(+bias) packed hi/lo bf16 -> outp
// MODE 1: A = packed bf16 (g_h1p); out: fused (relu(+bias)) @ W2 -> atomicAdd un
// Block tile 128(M) x 128(N), BK=32, 256 threads, warp grid 2(M) x 4(N).
#define STAGE_SZ 32768            // A 16KB + B 16KB
#define SM_BIAS  65536
#define SM_W2    66560
#define SMEM_SZ  68608

template <int KDIM, int MODE>
__global__ __launch_bounds__(256, 1) void gemm_tc(
    const float* __restrict__ Af, const __nv_bfloat16* __restrict__ Ap,
    const __nv_bfloat16* __restrict__ Wp, const float* __restrict__ bias,
    const float* __restrict__ W2, __nv_bfloat16* __restrict__ outp,
    float* __restrict__ un)
{
    extern __shared__ char smem[];
    constexpr int NC = KDIM / 32;
    const int tid = threadIdx.x;
    const int lane = tid & 31;
    const int wid = tid >> 5;
    const int warp_m = wid >> 2, warp_n = wid & 3;
    const int nBase = blockIdx.x * 128;
    const size_t mBase = (size_t)blockIdx.y * 128;

    const uint32_t sb = smem_u32(smem);
    float* biasS = (float*)(smem + SM_BIAS);
    float* W2s = (float*)(smem + SM_W2);
    if (tid < 128) biasS[tid] = bias[nBase + tid];
    if (MODE == 1) W2s[tid] = W2[nBase * 2 + tid];

    // per-thread copy roles
    const int crow = tid >> 1;       // 0..127
    const int chalf = tid & 1;       // 0/1
    const int cxor = crow & 7;

    // ldmatrix lane constants
    const uint32_t aRowOff = (uint32_t)(warp_m * 64 + (lane & 15)) * 128;
    const uint32_t aKsel = (uint32_t)(lane >> 4);
    const uint32_t bRowOff = (uint32_t)(warp_n * 32 + ((lane >> 4) << 3) + (lane & 7)) * 128;
    const uint32_t bKsel = (uint32_t)((lane >> 3) & 1);
    const uint32_t xr = (uint32_t)(lane & 7);

    float acc[4][4][4];
#pragma unroll
    for (int a = 0; a < 4; a++)
#pragma unroll
        for (int b = 0; b < 4; b++)
#pragma unroll
            for (int q = 0; q < 4; q++) acc[a][b][q] = 0.f;

    float rA[16];  // MODE0 staging

    // ---- copy helpers (as lambdas) ----
    auto loadA_regs = [&](int c) {
        const float* p = Af + (mBase + crow) * KDIM + c * 32 + chalf * 16;
#pragma unroll
        for (int q = 0; q < 4; q++)
            *(float4*)(rA + 4 * q) = *(const float4*)(p + 4 * q);
    };
    auto storeA_regs = [&](int stage) {
        uint32_t dst = sb + stage * STAGE_SZ + crow * 128;
        uint32_t hh[8], ll[8];
#pragma unroll
        for (int q = 0; q < 8; q++) split2(rA[2 * q], rA[2 * q + 1], hh[q], ll[q]);
        STS128(dst + (((chalf * 2 + 0)) ^ cxor) * 16, hh[0], hh[1], hh[2], hh[3]);
        STS128(dst + (((chalf * 2 + 1)) ^ cxor) * 16, hh[4], hh[5], hh[6], hh[7]);
        STS128(dst + ((4 + chalf * 2 + 0) ^ cxor) * 16, ll[0], ll[1], ll[2], ll[3]);
        STS128(dst + ((4 + chalf * 2 + 1) ^ cxor) * 16, ll[4], ll[5], ll[6], ll[7]);
    };
    auto cpA = [&](int c, int stage) {
        const char* src = (const char*)(Ap + ((size_t)c * M_ROWS + mBase + crow) * 64 + chalf * 32);
        uint32_t dst = sb + stage * STAGE_SZ + crow * 128;
#pragma unroll
        for (int j = 0; j < 4; j++)
            CP16(dst + ((chalf * 4 + j) ^ cxor) * 16, src + j * 16);
    };
    auto cpB = [&](int c, int stage) {
        const char* src = (const char*)(Wp + ((size_t)c * 256 + nBase + crow) * 64 + chalf * 32);
        uint32_t dst = sb + stage * STAGE_SZ + 16384 + crow * 128;
#pragma unroll
        for (int j = 0; j < 4; j++)
            CP16(dst + ((chalf * 4 + j) ^ cxor) * 16, src + j * 16);
    };
    auto compute = [&](int stage) {
        uint32_t Ab = sb + stage * STAGE_SZ + aRowOff;
        uint32_t Bb = sb + stage * STAGE_SZ + 16384 + bRowOff;
#pragma unroll
        for (int s = 0; s < 2; s++) {
            uint32_t ah[16], al[16], bh[8], bl[8];
#pragma unroll
            for (int mi = 0; mi < 4; mi++) {
                ldsm4(Ab + mi * 2048 + (((s * 2 + aKsel)) ^ xr) * 16, ah + 4 * mi);
                ldsm4(Ab + mi * 2048 + ((4 + s * 2 + aKsel) ^ xr) * 16, al + 4 * mi);
            }
#pragma unroll
            for (int nb = 0; nb < 2; nb++) {
                ldsm4(Bb + nb * 2048 + (((s * 2 + bKsel)) ^ xr) * 16, bh + 4 * nb);
                ldsm4(Bb + nb * 2048 + ((4 + s * 2 + bKsel) ^ xr) * 16, bl + 4 * nb);
            }
#pragma unroll
            for (int mi = 0; mi < 4; mi++)
#pragma unroll
                for (int nj = 0; nj < 4; nj++) {
                    float* cc = acc[mi][nj];
                    mma_bf16(cc, ah + 4 * mi, bh[2 * nj], bh[2 * nj + 1]);
                    mma_bf16(cc, ah + 4 * mi, bl[2 * nj], bl[2 * nj + 1]);
                    mma_bf16(cc, al + 4 * mi, bh[2 * nj], bh[2 * nj + 1]);
                }
        }
    };

    // ---- prologue ----
    if (MODE == 0) {
        loadA_regs(0);
        cpB(0, 0);
        CPCOMMIT();
        storeA_regs(0);
    } else {
        cpA(0, 0);
        cpB(0, 0);
        CPCOMMIT();
    }

    // ---- main loop ----
    for (int c = 0; c < NC; c++) {
        const int buf = c & 1, nbuf = buf ^ 1;
        CPWAIT0();
        __syncthreads();
        if (c + 1 < NC) {
            if (MODE == 0) {
                loadA_regs(c + 1);
                cpB(c + 1, nbuf);
            } else {
                cpA(c + 1, nbuf);
                cpB(c + 1, nbuf);
            }
            CPCOMMIT();
        }
        compute(buf);
        if (MODE == 0 && c + 1 < NC) storeA_regs(nbuf);
    }

    // ---- epilogue ----
    const int rloc = warp_m * 64 + (lane >> 2);
    const int nl0 = warp_n * 32 + (lane & 3) * 2;

    if (MODE == 0) {
#pragma unroll
        for (int mi = 0; mi < 4; mi++)
#pragma unroll
            for (int nj = 0; nj < 4; nj++) {
                int nl = nl0 + nj * 8;
                float b0v = biasS[nl], b1v = biasS[nl + 1];
                float v00 = fmaxf(acc[mi][nj][0] + b0v, 0.f);
                float v01 = fmaxf(acc[mi][nj][1] + b1v, 0.f);
                float v10 = fmaxf(acc[mi][nj][2] + b0v, 0.f);
                float v11 = fmaxf(acc[mi][nj][3] + b1v, 0.f);
                int gn = nBase + nl;
                int cpk = gn >> 5, slot = gn & 31;
                size_t r0 = mBase + rloc + mi * 16;
                size_t o0 = ((size_t)cpk * M_ROWS + r0) * 64 + slot;
                size_t o1 = o0 + 8 * 64;
                uint32_t h, l;
                split2(v00, v01, h, l);
                *(uint32_t*)(outp + o0) = h;
                *(uint32_t*)(outp + o0 + 32) = l;
                split2(v10, v11, h, l);
                *(uint32_t*)(outp + o1) = h;
                *(uint32_t*)(outp + o1 + 32) = l;
            }
    } else {
        float up[16];
#pragma unroll
        for (int i = 0; i < 16; i++) up[i] = 0.f;
#pragma unroll
        for (int mi = 0; mi < 4; mi++)
#pragma unroll
            for (int nj = 0; nj < 4; nj++) {
                int nl = nl0 + nj * 8;
                float b0v = biasS[nl], b1v = biasS[nl + 1];
                float w00 = W2s[2 * nl], w01 = W2s[2 * nl + 1];
                float w10 = W2s[2 * nl + 2], w11 = W2s[2 * nl + 3];
                float v00 = fmaxf(acc[mi][nj][0] + b0v, 0.f);
                float v01 = fmaxf(acc[mi][nj][1] + b1v, 0.f);
                float v10 = fmaxf(acc[mi][nj][2] + b0v, 0.f);
                float v11 = fmaxf(acc[mi][nj][3] + b1v, 0.f);
                up[mi * 4 + 0] += v00 * w00 + v01 * w10;
                up[mi * 4 + 1] += v00 * w01 + v01 * w11;
                up[mi * 4 + 2] += v10 * w00 + v11 * w10;
                up[mi * 4 + 3] += v10 * w01 + v11 * w11;
            }
#pragma unroll
        for (int k = 1; k <= 2; k <<= 1)
#pragma unroll
            for (int i = 0; i < 16; i++)
                up[i] += __shfl_xor_sync(0xffffffffu, up[i], k);
        if ((lane & 3) == 0) {
#pragma unroll
            for (int mi = 0; mi < 4; mi++) {
                size_t r0 = mBase + rloc + mi * 16;
                size_t r1 = r0 + 8;
                atomicAdd(&un[r0 * 2 + 0], up[mi * 4 + 0]);
                atomicAdd(&un[r0 * 2 + 1], up[mi * 4 + 1]);
                atomicAdd(&un[r1 * 2 + 0], up[mi * 4 + 2]);
                atomicAdd(&un[r1 * 2 + 1], up[mi * 4 + 3]);
            }
        }
    }
}

// -------- binary MLP + pairwise config sums ----------------------------------
__global__ __launch_bounds__(128) void binary_kernel(
    const float* __restrict__ ctx, const float* __restrict__ R0,
    const float* __restrict__ r0, const float* __restrict__ R1,
    const float* __restrict__ r1, float* __restrict__ pairsum)
{
    __shared__ float cd[NPAIR][5];
    __shared__ float R0s[5][RHv];
    __shared__ float r0s[RHv];
    __shared__ float R1s[RHv][3];
    __shared__ float r1s[3];
    __shared__ float h2s[NPAIR][RHv];
    __shared__ float bp4s[NPAIR][4];

    int b = blockIdx.x, t = threadIdx.x;
    for (int i = t; i < NPAIR * 5; i += 128) cd[i / 5][i % 5] = ctx[b * NPAIR * 5 + i];
    for (int i = t; i < 5 * RHv; i += 128) R0s[i / RHv][i % RHv] = R0[i];
    if (t < RHv) r0s[t] = r0[t];
    for (int i = t; i < RHv * 3; i += 128) R1s[i / 3][i % 3] = R1[i];
    if (t < 3) r1s[t] = r1[t];
    __syncthreads();

    for (int idx = t; idx < NPAIR * RHv; idx += 128) {
        int p = idx / RHv, u = idx % RHv;
        float v = r0s[u];
#pragma unroll
        for (int x = 0; x < 5; x++) v += cd[p][x] * R0s[x][u];
        h2s[p][u] = fmaxf(v, 0.f);
    }
    __syncthreads();

    if (t < NPAIR * 3) {
        int p = t / 3, y = t % 3;
        float v = r1s[y];
#pragma unroll
        for (int u = 0; u < RHv; u++) v += h2s[p][u] * R1s[u][y];
        if (y == 0) bp4s[p][0] = v;
        else if (y == 1) { bp4s[p][1] = v; bp4s[p][2] = v; }
        else bp4s[p][3] = v;
    }
    __syncthreads();

    int s = t;
    float accv = 0.f;
    int p = 0;
#pragma unroll
    for (int i = 0; i < NE; i++)
#pragma unroll
        for (int j = i + 1; j < NE; j++) {
            int bi = (s >> (6 - i)) & 1;
            int bj = (s >> (6 - j)) & 1;
            accv += bp4s[p][bi * 2 + bj];
            p++;
        }
    pairsum[(size_t)b * NCFG + s] = accv;
}

// ---------------- joint + lse + marginals: one warp per (n,b) -----------------
__global__ __launch_bounds__(256) void joint_kernel(
    const float* __restrict__ un, const float* __restrict__ ps,
    const float* __restrict__ b2v, float* __restrict__ out_marg,
    float* __restrict__ out_joint)
{
    int w = blockIdx.x * 8 + (threadIdx.x >> 5);  // 0..16383
    int lane = threadIdx.x & 31;
    int b = w & (BSZv - 1), n = w >> 9;
    size_t nb = (size_t)n * BSZv + b;

    float val = 0.f;
    if (lane < 14) val = un[nb * 14 + lane] + b2v[lane & 1];
    float u[14];
#pragma unroll
    for (int i = 0; i < 14; i++) u[i] = __shfl_sync(0xffffffffu, val, i);

    float j[4], e[4];
    float mx = -1e30f;
#pragma unroll
    for (int q = 0; q < 4; q++) {
        int s = q * 32 + lane;
        float t = ps[(size_t)b * NCFG + s];
#pragma unroll
        for (int i = 0; i < NE; i++) t += u[i * 2 + ((s >> (6 - i)) & 1)];
        j[q] = t;
        mx = fmaxf(mx, t);
    }
#pragma unroll
    for (int o = 16; o; o >>= 1) mx = fmaxf(mx, __shfl_xor_sync(0xffffffffu, mx, o));

    float p1[NE], p0[NE];
#pragma unroll
    for (int i = 0; i < NE; i++) { p1[i] = 0.f; p0[i] = 0.f; }
#pragma unroll
    for (int q = 0; q < 4; q++) {
        int s = q * 32 + lane;
        e[q] = __expf(j[q] - mx);
#pragma unroll
        for (int i = 0; i < NE; i++) {
            if ((s >> (6 - i)) & 1) p1[i] += e[q];
            else p0[i] += e[q];
        }
    }
#pragma unroll
    for (int o = 16; o; o >>= 1)
#pragma unroll
        for (int i = 0; i < NE; i++) {
            p1[i] += __shfl_xor_sync(0xffffffffu, p1[i], o);
            p0[i] += __shfl_xor_sync(0xffffffffu, p0[i], o);
        }

    float lt = __logf(p1[0] + p0[0]);
#pragma unroll
    for (int q = 0; q < 4; q++)
        out_joint[nb * NCFG + q * 32 + lane] = j[q] - mx - lt;
    if (lane < NE)
        out_marg[nb * NE + lane] = __logf(p1[lane]) - __logf(p0[lane]);
}

// ---------------- launch -------------------------------------------------------
extern "C" void kernel_launch(void* const* d_in, const int* in_sizes, int n_in,
                              void* d_out, int out_size)
{
    const float* input = (const float*)d_in[0];
    const float* ctx   = (const float*)d_in[1];
    const float* W0 = (const float*)d_in[4];
    const float* b0 = (const float*)d_in[5];
    const float* W1 = (const float*)d_in[6];
    const float* b1 = (const float*)d_in[7];
    const float* W2 = (const float*)d_in[8];
    const float* b2 = (const float*)d_in[9];
    const float* R0 = (const float*)d_in[10];
    const float* r0 = (const float*)d_in[11];
    const float* R1 = (const float*)d_in[12];
    const float* r1 = (const float*)d_in[13];

    float* out = (float*)d_out;
    float* out_marg = out;                    // [32,512,7]
    float* out_joint = out + (size_t)M_ROWS;  // [32,512,128]

    __nv_bfloat16 *w0p, *w1p, *h1p;
    float *un, *psum;
    cudaGetSymbolAddress((void**)&w0p, g_w0p);
    cudaGetSymbolAddress((void**)&w1p, g_w1p);
    cudaGetSymbolAddress((void**)&h1p, g_h1p);
    cudaGetSymbolAddress((void**)&un, g_un);
    cudaGetSymbolAddress((void**)&psum, g_pairsum);

    cudaFuncSetAttribute(gemm_tc<DIN, 0>, cudaFuncAttributeMaxDynamicSharedMemorySize, SMEM_SZ);
    cudaFuncSetAttribute(gemm_tc<DHv, 1>, cudaFuncAttributeMaxDynamicSharedMemorySize, SMEM_SZ);

    pack_weights<<<DIN, 256>>>(W0, w0p, DIN);
    pack_weights<<<DHv, 256>>>(W1, w1p, DHv);
    cudaMemsetAsync(un, 0, (size_t)M_ROWS * 2 * sizeof(float));

    gemm_tc<DIN, 0><<<dim3(2, M_ROWS / 128), 256, SMEM_SZ>>>(
        input, nullptr, w0p, b0, nullptr, h1p, nullptr);
    gemm_tc<DHv, 1><<<dim3(2, M_ROWS / 128), 256, SMEM_SZ>>>(
        nullptr, h1p, w1p, b1, W2, nullptr, un);
    binary_kernel<<<BSZv, 128>>>(ctx, R0, r0, R1, r1, psum);
    joint_kernel<<<(NN * BSZv) / 8, 256>>>(un, psum, b2, out_marg, out_joint);
}

// round 4
// speedup vs baseline: 2.3202x; 1.1330x over previous
#include <cuda_runtime.h>
#include <cuda_bf16.h>
#include <cstdint>
#include <math.h>

#define NN    32
#define BSZv  512
#define NE    7
#define DIN   512
#define DHv   256
#define RHv   64
#define NPAIR 21
#define M_ROWS (NN * BSZv * NE)   // 114688
#define NCFG  128

// ---------------- scratch (device globals; no allocation allowed) ------------
// packed layout: [k-chunk c][row][64 bf16 = hi(k 32) | lo(k 32)]  (128B per row)
__device__ __align__(128) __nv_bfloat16 g_w0p[(size_t)(DIN / 32) * DHv * 64];
__device__ __align__(128) __nv_bfloat16 g_w1p[(size_t)(DHv / 32) * DHv * 64];
__device__ __align__(128) __nv_bfloat16 g_h1p[(size_t)(DHv / 32) * M_ROWS * 64];
__device__ float g_un[(size_t)M_ROWS * 2];
__device__ float g_pairsum[(size_t)BSZv * NCFG];

// ---------------- PTX helpers ------------------------------------------------
__device__ __forceinline__ uint32_t smem_u32(const void* p) {
    uint32_t a;
    asm("{ .reg .u64 t; cvta.to.shared.u64 t, %1; cvt.u32.u64 %0, t; }" : "=r"(a) : "l"(p));
    return a;
}
__device__ __forceinline__ void ldsm4(uint32_t a, uint32_t* r) {
    asm volatile("ldmatrix.sync.aligned.m8n8.x4.shared.b16 {%0,%1,%2,%3}, [%4];"
                 : "=r"(r[0]), "=r"(r[1]), "=r"(r[2]), "=r"(r[3]) : "r"(a));
}
__device__ __forceinline__ void mma_bf16(float* c, const uint32_t* a, uint32_t b0, uint32_t b1) {
    asm volatile("mma.sync.aligned.m16n8k16.row.col.f32.bf16.bf16.f32 "
                 "{%0,%1,%2,%3}, {%4,%5,%6,%7}, {%8,%9}, {%0,%1,%2,%3};"
                 : "+f"(c[0]), "+f"(c[1]), "+f"(c[2]), "+f"(c[3])
                 : "r"(a[0]), "r"(a[1]), "r"(a[2]), "r"(a[3]), "r"(b0), "r"(b1));
}
#define CP16(dst, src) asm volatile("cp.async.cg.shared.global [%0], [%1], 16;" :: "r"(dst), "l"(src))
#define CPCOMMIT()     asm volatile("cp.async.commit_group;" ::: "memory")
#define CPWAIT0()      asm volatile("cp.async.wait_group 0;" ::: "memory")
#define STS128(a, v0, v1, v2, v3) \
    asm volatile("st.shared.v4.b32 [%0], {%1,%2,%3,%4};" :: "r"(a), "r"(v0), "r"(v1), "r"(v2), "r"(v3))

__device__ __forceinline__ uint32_t pack2(__nv_bfloat16 a, __nv_bfloat16 b) {
    __nv_bfloat162 t = __halves2bfloat162(a, b);
    return *reinterpret_cast<uint32_t*>(&t);
}
__device__ __forceinline__ void split2(float a, float b, uint32_t& h, uint32_t& l) {
    __nv_bfloat16 ha = __float2bfloat16_rn(a), hb = __float2bfloat16_rn(b);
    __nv_bfloat16 la = __float2bfloat16_rn(a - __bfloat162float(ha));
    __nv_bfloat16 lb = __float2bfloat16_rn(b - __bfloat162float(hb));
    h = pack2(ha, hb);
    l = pack2(la, lb);
}

// ---------------- weight packing ----------------------------------------------
__global__ __launch_bounds__(256) void pack_weights(
    const float* __restrict__ W, __nv_bfloat16* __restrict__ dst, int K)
{
    int idx = blockIdx.x * 256 + threadIdx.x;
    if (idx >= K * 256) return;
    int k = idx >> 8, n = idx & 255;
    float v = W[idx];
    __nv_bfloat16 h = __float2bfloat16_rn(v);
    __nv_bfloat16 l = __float2bfloat16_rn(v - __bfloat162float(h));
    size_t o = ((size_t)(k >> 5) * 256 + n) * 64 + (k & 31);
    dst[o] = h;
    dst[o + 32] = l;
}

// ---------------- GEMM (mma.sync bf16x3) --------------------------------------
// Block tile 128(M) x 128(N), BK=32, 256 threads, warp grid 2(M) x 4(N).
// 2 CTAs/SM: regs capped at 128 via launch_bounds, smem 67KB/CTA.
#define STAGE_SZ 32768            // A 16KB + B 16KB
#define SM_BIAS  65536            // 128 f32
#define SM_W2    66048            // 256 f32
#define SMEM_SZ  67072

template <int KDIM, int MODE>
__global__ __launch_bounds__(256, 2) void gemm_tc(
    const float* __restrict__ Af, const __nv_bfloat16* __restrict__ Ap,
    const __nv_bfloat16* __restrict__ Wp, const float* __restrict__ bias,
    const float* __restrict__ W2, __nv_bfloat16* __restrict__ outp,
    float* __restrict__ un)
{
    extern __shared__ char smem[];
    constexpr int NC = KDIM / 32;
    const int tid = threadIdx.x;
    const int lane = tid & 31;
    const int wid = tid >> 5;
    const int warp_m = wid >> 2, warp_n = wid & 3;
    const int nBase = blockIdx.x * 128;
    const size_t mBase = (size_t)blockIdx.y * 128;

    const uint32_t sb = smem_u32(smem);
    float* biasS = (float*)(smem + SM_BIAS);
    float* W2s = (float*)(smem + SM_W2);
    if (tid < 128) biasS[tid] = bias[nBase + tid];
    if (MODE == 1) W2s[tid] = W2[nBase * 2 + tid];

    const int crow = tid >> 1;       // 0..127
    const int chalf = tid & 1;       // 0/1
    const int cxor = crow & 7;

    const uint32_t aRowOff = (uint32_t)(warp_m * 64 + (lane & 15)) * 128;
    const uint32_t aKsel = (uint32_t)(lane >> 4);
    const uint32_t bRowOff = (uint32_t)(warp_n * 32 + ((lane >> 4) << 3) + (lane & 7)) * 128;
    const uint32_t bKsel = (uint32_t)((lane >> 3) & 1);
    const uint32_t xr = (uint32_t)(lane & 7);

    float acc[4][4][4];
#pragma unroll
    for (int a = 0; a < 4; a++)
#pragma unroll
        for (int b = 0; b < 4; b++)
#pragma unroll
            for (int q = 0; q < 4; q++) acc[a][b][q] = 0.f;

    // MODE0: fp32 A -> split -> STS, two 8-float half passes (low reg pressure)
    auto stageA_direct = [&](int c, int stg) {
        const float* p = Af + (mBase + crow) * KDIM + c * 32 + chalf * 16;
        uint32_t dst = sb + stg * STAGE_SZ + crow * 128;
#pragma unroll
        for (int h = 0; h < 2; h++) {
            float v[8];
            *(float4*)(v) = *(const float4*)(p + 8 * h);
            *(float4*)(v + 4) = *(const float4*)(p + 8 * h + 4);
            uint32_t hh[4], ll[4];
#pragma unroll
            for (int q = 0; q < 4; q++) split2(v[2 * q], v[2 * q + 1], hh[q], ll[q]);
            STS128(dst + ((chalf * 2 + h) ^ cxor) * 16, hh[0], hh[1], hh[2], hh[3]);
            STS128(dst + ((4 + chalf * 2 + h) ^ cxor) * 16, ll[0], ll[1], ll[2], ll[3]);
        }
    };
    auto cpA = [&](int c, int stage) {
        const char* src = (const char*)(Ap + ((size_t)c * M_ROWS + mBase + crow) * 64 + chalf * 32);
        uint32_t dst = sb + stage * STAGE_SZ + crow * 128;
#pragma unroll
        for (int j = 0; j < 4; j++)
            CP16(dst + ((chalf * 4 + j) ^ cxor) * 16, src + j * 16);
    };
    auto cpB = [&](int c, int stage) {
        const char* src = (const char*)(Wp + ((size_t)c * 256 + nBase + crow) * 64 + chalf * 32);
        uint32_t dst = sb + stage * STAGE_SZ + 16384 + crow * 128;
#pragma unroll
        for (int j = 0; j < 4; j++)
            CP16(dst + ((chalf * 4 + j) ^ cxor) * 16, src + j * 16);
    };
    // B-fragments first (16 regs), then stream A per-mi (8 regs): peak live ~100
    auto compute = [&](int stage) {
        uint32_t Ab = sb + stage * STAGE_SZ + aRowOff;
        uint32_t Bb = sb + stage * STAGE_SZ + 16384 + bRowOff;
#pragma unroll
        for (int s = 0; s < 2; s++) {
            uint32_t bh[8], bl[8];
#pragma unroll
            for (int nb = 0; nb < 2; nb++) {
                ldsm4(Bb + nb * 2048 + (((s * 2 + bKsel)) ^ xr) * 16, bh + 4 * nb);
                ldsm4(Bb + nb * 2048 + ((4 + s * 2 + bKsel) ^ xr) * 16, bl + 4 * nb);
            }
#pragma unroll
            for (int mi = 0; mi < 4; mi++) {
                uint32_t ah[4], al[4];
                ldsm4(Ab + mi * 2048 + (((s * 2 + aKsel)) ^ xr) * 16, ah);
                ldsm4(Ab + mi * 2048 + ((4 + s * 2 + aKsel) ^ xr) * 16, al);
#pragma unroll
                for (int nj = 0; nj < 4; nj++) {
                    float* cc = acc[mi][nj];
                    mma_bf16(cc, ah, bh[2 * nj], bh[2 * nj + 1]);
                    mma_bf16(cc, ah, bl[2 * nj], bl[2 * nj + 1]);
                    mma_bf16(cc, al, bh[2 * nj], bh[2 * nj + 1]);
                }
            }
        }
    };

    // ---- prologue ----
    if (MODE == 0) {
        cpB(0, 0);
        CPCOMMIT();
        stageA_direct(0, 0);
    } else {
        cpA(0, 0);
        cpB(0, 0);
        CPCOMMIT();
    }

    // ---- main loop ----
    for (int c = 0; c < NC; c++) {
        const int buf = c & 1, nbuf = buf ^ 1;
        CPWAIT0();
        __syncthreads();
        if (c + 1 < NC) {
            if (MODE == 0) {
                cpB(c + 1, nbuf);
                CPCOMMIT();
                stageA_direct(c + 1, nbuf);   // LDG+split overlaps other CTA's MMA
            } else {
                cpA(c + 1, nbuf);
                cpB(c + 1, nbuf);
                CPCOMMIT();
            }
        }
        compute(buf);
    }

    // ---- epilogue ----
    const int rloc = warp_m * 64 + (lane >> 2);
    const int nl0 = warp_n * 32 + (lane & 3) * 2;

    if (MODE == 0) {
#pragma unroll
        for (int mi = 0; mi < 4; mi++)
#pragma unroll
            for (int nj = 0; nj < 4; nj++) {
                int nl = nl0 + nj * 8;
                float b0v = biasS[nl], b1v = biasS[nl + 1];
                float v00 = fmaxf(acc[mi][nj][0] + b0v, 0.f);
                float v01 = fmaxf(acc[mi][nj][1] + b1v, 0.f);
                float v10 = fmaxf(acc[mi][nj][2] + b0v, 0.f);
                float v11 = fmaxf(acc[mi][nj][3] + b1v, 0.f);
                int gn = nBase + nl;
                int cpk = gn >> 5, slot = gn & 31;
                size_t r0 = mBase + rloc + mi * 16;
                size_t o0 = ((size_t)cpk * M_ROWS + r0) * 64 + slot;
                size_t o1 = o0 + 8 * 64;
                uint32_t h, l;
                split2(v00, v01, h, l);
                *(uint32_t*)(outp + o0) = h;
                *(uint32_t*)(outp + o0 + 32) = l;
                split2(v10, v11, h, l);
                *(uint32_t*)(outp + o1) = h;
                *(uint32_t*)(outp + o1 + 32) = l;
            }
    } else {
        float up[16];
#pragma unroll
        for (int i = 0; i < 16; i++) up[i] = 0.f;
#pragma unroll
        for (int mi = 0; mi < 4; mi++)
#pragma unroll
            for (int nj = 0; nj < 4; nj++) {
                int nl = nl0 + nj * 8;
                float b0v = biasS[nl], b1v = biasS[nl + 1];
                float w00 = W2s[2 * nl], w01 = W2s[2 * nl + 1];
                float w10 = W2s[2 * nl + 2], w11 = W2s[2 * nl + 3];
                float v00 = fmaxf(acc[mi][nj][0] + b0v, 0.f);
                float v01 = fmaxf(acc[mi][nj][1] + b1v, 0.f);
                float v10 = fmaxf(acc[mi][nj][2] + b0v, 0.f);
                float v11 = fmaxf(acc[mi][nj][3] + b1v, 0.f);
                up[mi * 4 + 0] += v00 * w00 + v01 * w10;
                up[mi * 4 + 1] += v00 * w01 + v01 * w11;
                up[mi * 4 + 2] += v10 * w00 + v11 * w10;
                up[mi * 4 + 3] += v10 * w01 + v11 * w11;
            }
#pragma unroll
        for (int k = 1; k <= 2; k <<= 1)
#pragma unroll
            for (int i = 0; i < 16; i++)
                up[i] += __shfl_xor_sync(0xffffffffu, up[i], k);
        if ((lane & 3) == 0) {
#pragma unroll
            for (int mi = 0; mi < 4; mi++) {
                size_t r0 = mBase + rloc + mi * 16;
                size_t r1 = r0 + 8;
                atomicAdd(&un[r0 * 2 + 0], up[mi * 4 + 0]);
                atomicAdd(&un[r0 * 2 + 1], up[mi * 4 + 1]);
                atomicAdd(&un[r1 * 2 + 0], up[mi * 4 + 2]);
                atomicAdd(&un[r1 * 2 + 1], up[mi * 4 + 3]);
            }
        }
    }
}

// -------- binary MLP + pairwise config sums ----------------------------------
__global__ __launch_bounds__(128) void binary_kernel(
    const float* __restrict__ ctx, const float* __restrict__ R0,
    const float* __restrict__ r0, const float* __restrict__ R1,
    const float* __restrict__ r1, float* __restrict__ pairsum)
{
    __shared__ float cd[NPAIR][5];
    __shared__ float R0s[5][RHv];
    __shared__ float r0s[RHv];
    __shared__ float R1s[RHv][3];
    __shared__ float r1s[3];
    __shared__ float h2s[NPAIR][RHv];
    __shared__ float bp4s[NPAIR][4];

    int b = blockIdx.x, t = threadIdx.x;
    for (int i = t; i < NPAIR * 5; i += 128) cd[i / 5][i % 5] = ctx[b * NPAIR * 5 + i];
    for (int i = t; i < 5 * RHv; i += 128) R0s[i / RHv][i % RHv] = R0[i];
    if (t < RHv) r0s[t] = r0[t];
    for (int i = t; i < RHv * 3; i += 128) R1s[i / 3][i % 3] = R1[i];
    if (t < 3) r1s[t] = r1[t];
    __syncthreads();

    for (int idx = t; idx < NPAIR * RHv; idx += 128) {
        int p = idx / RHv, u = idx % RHv;
        float v = r0s[u];
#pragma unroll
        for (int x = 0; x < 5; x++) v += cd[p][x] * R0s[x][u];
        h2s[p][u] = fmaxf(v, 0.f);
    }
    __syncthreads();

    if (t < NPAIR * 3) {
        int p = t / 3, y = t % 3;
        float v = r1s[y];
#pragma unroll
        for (int u = 0; u < RHv; u++) v += h2s[p][u] * R1s[u][y];
        if (y == 0) bp4s[p][0] = v;
        else if (y == 1) { bp4s[p][1] = v; bp4s[p][2] = v; }
        else bp4s[p][3] = v;
    }
    __syncthreads();

    int s = t;
    float accv = 0.f;
    int p = 0;
#pragma unroll
    for (int i = 0; i < NE; i++)
#pragma unroll
        for (int j = i + 1; j < NE; j++) {
            int bi = (s >> (6 - i)) & 1;
            int bj = (s >> (6 - j)) & 1;
            accv += bp4s[p][bi * 2 + bj];
            p++;
        }
    pairsum[(size_t)b * NCFG + s] = accv;
}

// ---------------- joint + lse + marginals: one warp per (n,b) -----------------
__global__ __launch_bounds__(256) void joint_kernel(
    const float* __restrict__ un, const float* __restrict__ ps,
    const float* __restrict__ b2v, float* __restrict__ out_marg,
    float* __restrict__ out_joint)
{
    int w = blockIdx.x * 8 + (threadIdx.x >> 5);
    int lane = threadIdx.x & 31;
    int b = w & (BSZv - 1), n = w >> 9;
    size_t nb = (size_t)n * BSZv + b;

    float val = 0.f;
    if (lane < 14) val = un[nb * 14 + lane] + b2v[lane & 1];
    float u[14];
#pragma unroll
    for (int i = 0; i < 14; i++) u[i] = __shfl_sync(0xffffffffu, val, i);

    float j[4], e[4];
    float mx = -1e30f;
#pragma unroll
    for (int q = 0; q < 4; q++) {
        int s = q * 32 + lane;
        float t = ps[(size_t)b * NCFG + s];
#pragma unroll
        for (int i = 0; i < NE; i++) t += u[i * 2 + ((s >> (6 - i)) & 1)];
        j[q] = t;
        mx = fmaxf(mx, t);
    }
#pragma unroll
    for (int o = 16; o; o >>= 1) mx = fmaxf(mx, __shfl_xor_sync(0xffffffffu, mx, o));

    float p1[NE], p0[NE];
#pragma unroll
    for (int i = 0; i < NE; i++) { p1[i] = 0.f; p0[i] = 0.f; }
#pragma unroll
    for (int q = 0; q < 4; q++) {
        int s = q * 32 + lane;
        e[q] = __expf(j[q] - mx);
#pragma unroll
        for (int i = 0; i < NE; i++) {
            if ((s >> (6 - i)) & 1) p1[i] += e[q];
            else p0[i] += e[q];
        }
    }
#pragma unroll
    for (int o = 16; o; o >>= 1)
#pragma unroll
        for (int i = 0; i < NE; i++) {
            p1[i] += __shfl_xor_sync(0xffffffffu, p1[i], o);
            p0[i] += __shfl_xor_sync(0xffffffffu, p0[i], o);
        }

    float lt = __logf(p1[0] + p0[0]);
#pragma unroll
    for (int q = 0; q < 4; q++)
        out_joint[nb * NCFG + q * 32 + lane] = j[q] - mx - lt;
    if (lane < NE)
        out_marg[nb * NE + lane] = __logf(p1[lane]) - __logf(p0[lane]);
}

// ---------------- launch -------------------------------------------------------
extern "C" void kernel_launch(void* const* d_in, const int* in_sizes, int n_in,
                              void* d_out, int out_size)
{
    const float* input = (const float*)d_in[0];
    const float* ctx   = (const float*)d_in[1];
    const float* W0 = (const float*)d_in[4];
    const float* b0 = (const float*)d_in[5];
    const float* W1 = (const float*)d_in[6];
    const float* b1 = (const float*)d_in[7];
    const float* W2 = (const float*)d_in[8];
    const float* b2 = (const float*)d_in[9];
    const float* R0 = (const float*)d_in[10];
    const float* r0 = (const float*)d_in[11];
    const float* R1 = (const float*)d_in[12];
    const float* r1 = (const float*)d_in[13];

    float* out = (float*)d_out;
    float* out_marg = out;
    float* out_joint = out + (size_t)M_ROWS;

    __nv_bfloat16 *w0p, *w1p, *h1p;
    float *un, *psum;
    cudaGetSymbolAddress((void**)&w0p, g_w0p);
    cudaGetSymbolAddress((void**)&w1p, g_w1p);
    cudaGetSymbolAddress((void**)&h1p, g_h1p);
    cudaGetSymbolAddress((void**)&un, g_un);
    cudaGetSymbolAddress((void**)&psum, g_pairsum);

    cudaFuncSetAttribute(gemm_tc<DIN, 0>, cudaFuncAttributeMaxDynamicSharedMemorySize, SMEM_SZ);
    cudaFuncSetAttribute(gemm_tc<DHv, 1>, cudaFuncAttributeMaxDynamicSharedMemorySize, SMEM_SZ);

    pack_weights<<<DIN, 256>>>(W0, w0p, DIN);
    pack_weights<<<DHv, 256>>>(W1, w1p, DHv);
    cudaMemsetAsync(un, 0, (size_t)M_ROWS * 2 * sizeof(float));

    gemm_tc<DIN, 0><<<dim3(2, M_ROWS / 128), 256, SMEM_SZ>>>(
        input, nullptr, w0p, b0, nullptr, h1p, nullptr);
    gemm_tc<DHv, 1><<<dim3(2, M_ROWS / 128), 256, SMEM_SZ>>>(
        nullptr, h1p, w1p, b1, W2, nullptr, un);
    binary_kernel<<<BSZv, 128>>>(ctx, R0, r0, R1, r1, psum);
    joint_kernel<<<(NN * BSZv) / 8, 256>>>(un, psum, b2, out_marg, out_joint);
}

// round 5
// speedup vs baseline: 2.3339x; 1.0059x over previous
#include <cuda_runtime.h>
#include <cuda_bf16.h>
#include <cstdint>
#include <math.h>

#define NN    32
#define BSZv  512
#define NE    7
#define DIN   512
#define DHv   256
#define RHv   64
#define NPAIR 21
#define M_ROWS (NN * BSZv * NE)   // 114688
#define NCFG  128

// ---------------- scratch (device globals; no allocation allowed) ------------
// packed layout: [k-chunk c][row][64 bf16 = hi(k 32) | lo(k 32)]  (128B per row)
__device__ __align__(128) __nv_bfloat16 g_w0p[(size_t)(DIN / 32) * DHv * 64];
__device__ __align__(128) __nv_bfloat16 g_w1p[(size_t)(DHv / 32) * DHv * 64];
__device__ __align__(128) __nv_bfloat16 g_h1p[(size_t)(DHv / 32) * M_ROWS * 64];
__device__ float g_un[(size_t)M_ROWS * 2];
__device__ float g_pairsum[(size_t)BSZv * NCFG];

// ---------------- PTX helpers ------------------------------------------------
__device__ __forceinline__ uint32_t smem_u32(const void* p) {
    uint32_t a;
    asm("{ .reg .u64 t; cvta.to.shared.u64 t, %1; cvt.u32.u64 %0, t; }" : "=r"(a) : "l"(p));
    return a;
}
__device__ __forceinline__ void ldsm4(uint32_t a, uint32_t* r) {
    asm volatile("ldmatrix.sync.aligned.m8n8.x4.shared.b16 {%0,%1,%2,%3}, [%4];"
                 : "=r"(r[0]), "=r"(r[1]), "=r"(r[2]), "=r"(r[3]) : "r"(a));
}
__device__ __forceinline__ void mma_bf16(float* c, const uint32_t* a, uint32_t b0, uint32_t b1) {
    asm volatile("mma.sync.aligned.m16n8k16.row.col.f32.bf16.bf16.f32 "
                 "{%0,%1,%2,%3}, {%4,%5,%6,%7}, {%8,%9}, {%0,%1,%2,%3};"
                 : "+f"(c[0]), "+f"(c[1]), "+f"(c[2]), "+f"(c[3])
                 : "r"(a[0]), "r"(a[1]), "r"(a[2]), "r"(a[3]), "r"(b0), "r"(b1));
}
#define CP16(dst, src) asm volatile("cp.async.cg.shared.global [%0], [%1], 16;" :: "r"(dst), "l"(src))
#define CPCOMMIT()     asm volatile("cp.async.commit_group;" ::: "memory")
#define CPWAIT0()      asm volatile("cp.async.wait_group 0;" ::: "memory")
#define CPWAIT1()      asm volatile("cp.async.wait_group 1;" ::: "memory")
#define STS128(a, v0, v1, v2, v3) \
    asm volatile("st.shared.v4.b32 [%0], {%1,%2,%3,%4};" :: "r"(a), "r"(v0), "r"(v1), "r"(v2), "r"(v3))

__device__ __forceinline__ uint32_t pack2(__nv_bfloat16 a, __nv_bfloat16 b) {
    __nv_bfloat162 t = __halves2bfloat162(a, b);
    return *reinterpret_cast<uint32_t*>(&t);
}
__device__ __forceinline__ void split2(float a, float b, uint32_t& h, uint32_t& l) {
    __nv_bfloat16 ha = __float2bfloat16_rn(a), hb = __float2bfloat16_rn(b);
    __nv_bfloat16 la = __float2bfloat16_rn(a - __bfloat162float(ha));
    __nv_bfloat16 lb = __float2bfloat16_rn(b - __bfloat162float(hb));
    h = pack2(ha, hb);
    l = pack2(la, lb);
}

// ---------------- weight packing ----------------------------------------------
__global__ __launch_bounds__(256) void pack_weights(
    const float* __restrict__ W, __nv_bfloat16* __restrict__ dst, int K)
{
    int idx = blockIdx.x * 256 + threadIdx.x;
    if (idx >= K * 256) return;
    int k = idx >> 8, n = idx & 255;
    float v = W[idx];
    __nv_bfloat16 h = __float2bfloat16_rn(v);
    __nv_bfloat16 l = __float2bfloat16_rn(v - __bfloat162float(h));
    size_t o = ((size_t)(k >> 5) * 256 + n) * 64 + (k & 31);
    dst[o] = h;
    dst[o + 32] = l;
}

// ---------------- GEMM (mma.sync bf16x3, 3-stage cp.async) --------------------
// Block tile 128(M) x 128(N), BK=32, 256 threads, warp grid 2(M) x 4(N).
// 2 CTAs/SM: regs capped at 128, smem ~98KB/CTA.
#define NSTAGE   3
#define STAGE_SZ 32768            // A 16KB + B 16KB
#define SM_BIAS  (NSTAGE * STAGE_SZ)          // 128 f32
#define SM_W2    (SM_BIAS + 512)              // 256 f32
#define SMEM_SZ  (SM_W2 + 1024)

template <int KDIM, int MODE>
__global__ __launch_bounds__(256, 2) void gemm_tc(
    const float* __restrict__ Af, const __nv_bfloat16* __restrict__ Ap,
    const __nv_bfloat16* __restrict__ Wp, const float* __restrict__ bias,
    const float* __restrict__ W2, __nv_bfloat16* __restrict__ outp,
    float* __restrict__ un)
{
    extern __shared__ char smem[];
    constexpr int NC = KDIM / 32;
    const int tid = threadIdx.x;
    const int lane = tid & 31;
    const int wid = tid >> 5;
    const int warp_m = wid >> 2, warp_n = wid & 3;
    const int nBase = blockIdx.x * 128;
    const size_t mBase = (size_t)blockIdx.y * 128;

    const uint32_t sb = smem_u32(smem);
    float* biasS = (float*)(smem + SM_BIAS);
    float* W2s = (float*)(smem + SM_W2);
    if (tid < 128) biasS[tid] = bias[nBase + tid];
    if (MODE == 1) W2s[tid] = W2[nBase * 2 + tid];

    const int crow = tid >> 1;       // 0..127
    const int chalf = tid & 1;       // 0/1
    const int cxor = crow & 7;

    const uint32_t aRowOff = (uint32_t)(warp_m * 64 + (lane & 15)) * 128;
    const uint32_t aKsel = (uint32_t)(lane >> 4);
    const uint32_t bRowOff = (uint32_t)(warp_n * 32 + ((lane >> 4) << 3) + (lane & 7)) * 128;
    const uint32_t bKsel = (uint32_t)((lane >> 3) & 1);
    const uint32_t xr = (uint32_t)(lane & 7);

    float acc[4][4][4];
#pragma unroll
    for (int a = 0; a < 4; a++)
#pragma unroll
        for (int b = 0; b < 4; b++)
#pragma unroll
            for (int q = 0; q < 4; q++) acc[a][b][q] = 0.f;

    float rA[16];   // MODE0: fp32 staging regs, LDG hoisted above compute

    auto loadA_regs = [&](int c) {
        const float* p = Af + (mBase + crow) * KDIM + c * 32 + chalf * 16;
        *(float4*)(rA)      = *(const float4*)(p);
        *(float4*)(rA + 4)  = *(const float4*)(p + 4);
        *(float4*)(rA + 8)  = *(const float4*)(p + 8);
        *(float4*)(rA + 12) = *(const float4*)(p + 12);
    };
    auto storeA_regs = [&](int stg) {
        uint32_t dst = sb + stg * STAGE_SZ + crow * 128;
        uint32_t hh[8], ll[8];
#pragma unroll
        for (int q = 0; q < 8; q++) split2(rA[2 * q], rA[2 * q + 1], hh[q], ll[q]);
        STS128(dst + ((chalf * 2 + 0) ^ cxor) * 16, hh[0], hh[1], hh[2], hh[3]);
        STS128(dst + ((chalf * 2 + 1) ^ cxor) * 16, hh[4], hh[5], hh[6], hh[7]);
        STS128(dst + ((4 + chalf * 2 + 0) ^ cxor) * 16, ll[0], ll[1], ll[2], ll[3]);
        STS128(dst + ((4 + chalf * 2 + 1) ^ cxor) * 16, ll[4], ll[5], ll[6], ll[7]);
    };
    auto cpA = [&](int c, int stage) {
        const char* src = (const char*)(Ap + ((size_t)c * M_ROWS + mBase + crow) * 64 + chalf * 32);
        uint32_t dst = sb + stage * STAGE_SZ + crow * 128;
#pragma unroll
        for (int j = 0; j < 4; j++)
            CP16(dst + ((chalf * 4 + j) ^ cxor) * 16, src + j * 16);
    };
    auto cpB = [&](int c, int stage) {
        const char* src = (const char*)(Wp + ((size_t)c * 256 + nBase + crow) * 64 + chalf * 32);
        uint32_t dst = sb + stage * STAGE_SZ + 16384 + crow * 128;
#pragma unroll
        for (int j = 0; j < 4; j++)
            CP16(dst + ((chalf * 4 + j) ^ cxor) * 16, src + j * 16);
    };
    auto compute = [&](int stage) {
        uint32_t Ab = sb + stage * STAGE_SZ + aRowOff;
        uint32_t Bb = sb + stage * STAGE_SZ + 16384 + bRowOff;
#pragma unroll
        for (int s = 0; s < 2; s++) {
            uint32_t bh[8], bl[8];
#pragma unroll
            for (int nb = 0; nb < 2; nb++) {
                ldsm4(Bb + nb * 2048 + (((s * 2 + bKsel)) ^ xr) * 16, bh + 4 * nb);
                ldsm4(Bb + nb * 2048 + ((4 + s * 2 + bKsel) ^ xr) * 16, bl + 4 * nb);
            }
#pragma unroll
            for (int mi = 0; mi < 4; mi++) {
                uint32_t ah[4], al[4];
                ldsm4(Ab + mi * 2048 + (((s * 2 + aKsel)) ^ xr) * 16, ah);
                ldsm4(Ab + mi * 2048 + ((4 + s * 2 + aKsel) ^ xr) * 16, al);
#pragma unroll
                for (int nj = 0; nj < 4; nj++) {
                    float* cc = acc[mi][nj];
                    mma_bf16(cc, ah, bh[2 * nj], bh[2 * nj + 1]);
                    mma_bf16(cc, ah, bl[2 * nj], bl[2 * nj + 1]);
                    mma_bf16(cc, al, bh[2 * nj], bh[2 * nj + 1]);
                }
            }
        }
    };

    // ---- prologue: prefetch chunks 0 and 1 ----
    if (MODE == 0) {
        cpB(0, 0); CPCOMMIT();
        cpB(1, 1); CPCOMMIT();
        loadA_regs(0);
        storeA_regs(0);                 // stage0 A ready (published by 1st sync)
        loadA_regs(1);                  // chunk1 A in regs; STS after compute(0)
    } else {
        cpA(0, 0); cpB(0, 0); CPCOMMIT();
        cpA(1, 1); cpB(1, 1); CPCOMMIT();
    }

    // ---- main loop: 3-stage, prefetch 2 ahead ----
    for (int c = 0; c < NC; c++) {
        const int stg = c % NSTAGE;
        if (c + 2 <= NC) CPWAIT1(); else CPWAIT0();
        __syncthreads();
        if (MODE == 0) {
            if (c + 2 < NC) { cpB(c + 2, (c + 2) % NSTAGE); CPCOMMIT(); }
            compute(stg);
            if (c + 1 < NC) {
                storeA_regs((c + 1) % NSTAGE);   // split+STS of rA(c+1)
                if (c + 2 < NC) loadA_regs(c + 2);  // LDG hidden under next compute
            }
        } else {
            if (c + 2 < NC) { cpA(c + 2, (c + 2) % NSTAGE); cpB(c + 2, (c + 2) % NSTAGE); CPCOMMIT(); }
            compute(stg);
        }
    }

    // ---- epilogue ----
    const int rloc = warp_m * 64 + (lane >> 2);
    const int nl0 = warp_n * 32 + (lane & 3) * 2;

    if (MODE == 0) {
#pragma unroll
        for (int mi = 0; mi < 4; mi++)
#pragma unroll
            for (int nj = 0; nj < 4; nj++) {
                int nl = nl0 + nj * 8;
                float b0v = biasS[nl], b1v = biasS[nl + 1];
                float v00 = fmaxf(acc[mi][nj][0] + b0v, 0.f);
                float v01 = fmaxf(acc[mi][nj][1] + b1v, 0.f);
                float v10 = fmaxf(acc[mi][nj][2] + b0v, 0.f);
                float v11 = fmaxf(acc[mi][nj][3] + b1v, 0.f);
                int gn = nBase + nl;
                int cpk = gn >> 5, slot = gn & 31;
                size_t r0 = mBase + rloc + mi * 16;
                size_t o0 = ((size_t)cpk * M_ROWS + r0) * 64 + slot;
                size_t o1 = o0 + 8 * 64;
                uint32_t h, l;
                split2(v00, v01, h, l);
                *(uint32_t*)(outp + o0) = h;
                *(uint32_t*)(outp + o0 + 32) = l;
                split2(v10, v11, h, l);
                *(uint32_t*)(outp + o1) = h;
                *(uint32_t*)(outp + o1 + 32) = l;
            }
    } else {
        float up[16];
#pragma unroll
        for (int i = 0; i < 16; i++) up[i] = 0.f;
#pragma unroll
        for (int mi = 0; mi < 4; mi++)
#pragma unroll
            for (int nj = 0; nj < 4; nj++) {
                int nl = nl0 + nj * 8;
                float b0v = biasS[nl], b1v = biasS[nl + 1];
                float w00 = W2s[2 * nl], w01 = W2s[2 * nl + 1];
                float w10 = W2s[2 * nl + 2], w11 = W2s[2 * nl + 3];
                float v00 = fmaxf(acc[mi][nj][0] + b0v, 0.f);
                float v01 = fmaxf(acc[mi][nj][1] + b1v, 0.f);
                float v10 = fmaxf(acc[mi][nj][2] + b0v, 0.f);
                float v11 = fmaxf(acc[mi][nj][3] + b1v, 0.f);
                up[mi * 4 + 0] += v00 * w00 + v01 * w10;
                up[mi * 4 + 1] += v00 * w01 + v01 * w11;
                up[mi * 4 + 2] += v10 * w00 + v11 * w10;
                up[mi * 4 + 3] += v10 * w01 + v11 * w11;
            }
#pragma unroll
        for (int k = 1; k <= 2; k <<= 1)
#pragma unroll
            for (int i = 0; i < 16; i++)
                up[i] += __shfl_xor_sync(0xffffffffu, up[i], k);
        if ((lane & 3) == 0) {
#pragma unroll
            for (int mi = 0; mi < 4; mi++) {
                size_t r0 = mBase + rloc + mi * 16;
                size_t r1 = r0 + 8;
                atomicAdd(&un[r0 * 2 + 0], up[mi * 4 + 0]);
                atomicAdd(&un[r0 * 2 + 1], up[mi * 4 + 1]);
                atomicAdd(&un[r1 * 2 + 0], up[mi * 4 + 2]);
                atomicAdd(&un[r1 * 2 + 1], up[mi * 4 + 3]);
            }
        }
    }
}

// -------- binary MLP + pairwise config sums ----------------------------------
__global__ __launch_bounds__(128) void binary_kernel(
    const float* __restrict__ ctx, const float* __restrict__ R0,
    const float* __restrict__ r0, const float* __restrict__ R1,
    const float* __restrict__ r1, float* __restrict__ pairsum)
{
    __shared__ float cd[NPAIR][5];
    __shared__ float R0s[5][RHv];
    __shared__ float r0s[RHv];
    __shared__ float R1s[RHv][3];
    __shared__ float r1s[3];
    __shared__ float h2s[NPAIR][RHv];
    __shared__ float bp4s[NPAIR][4];

    int b = blockIdx.x, t = threadIdx.x;
    for (int i = t; i < NPAIR * 5; i += 128) cd[i / 5][i % 5] = ctx[b * NPAIR * 5 + i];
    for (int i = t; i < 5 * RHv; i += 128) R0s[i / RHv][i % RHv] = R0[i];
    if (t < RHv) r0s[t] = r0[t];
    for (int i = t; i < RHv * 3; i += 128) R1s[i / 3][i % 3] = R1[i];
    if (t < 3) r1s[t] = r1[t];
    __syncthreads();

    for (int idx = t; idx < NPAIR * RHv; idx += 128) {
        int p = idx / RHv, u = idx % RHv;
        float v = r0s[u];
#pragma unroll
        for (int x = 0; x < 5; x++) v += cd[p][x] * R0s[x][u];
        h2s[p][u] = fmaxf(v, 0.f);
    }
    __syncthreads();

    if (t < NPAIR * 3) {
        int p = t / 3, y = t % 3;
        float v = r1s[y];
#pragma unroll
        for (int u = 0; u < RHv; u++) v += h2s[p][u] * R1s[u][y];
        if (y == 0) bp4s[p][0] = v;
        else if (y == 1) { bp4s[p][1] = v; bp4s[p][2] = v; }
        else bp4s[p][3] = v;
    }
    __syncthreads();

    int s = t;
    float accv = 0.f;
    int p = 0;
#pragma unroll
    for (int i = 0; i < NE; i++)
#pragma unroll
        for (int j = i + 1; j < NE; j++) {
            int bi = (s >> (6 - i)) & 1;
            int bj = (s >> (6 - j)) & 1;
            accv += bp4s[p][bi * 2 + bj];
            p++;
        }
    pairsum[(size_t)b * NCFG + s] = accv;
}

// ---------------- joint + lse + marginals: one warp per (n,b) -----------------
__global__ __launch_bounds__(256) void joint_kernel(
    const float* __restrict__ un, const float* __restrict__ ps,
    const float* __restrict__ b2v, float* __restrict__ out_marg,
    float* __restrict__ out_joint)
{
    int w = blockIdx.x * 8 + (threadIdx.x >> 5);
    int lane = threadIdx.x & 31;
    int b = w & (BSZv - 1), n = w >> 9;
    size_t nb = (size_t)n * BSZv + b;

    float val = 0.f;
    if (lane < 14) val = un[nb * 14 + lane] + b2v[lane & 1];
    float u[14];
#pragma unroll
    for (int i = 0; i < 14; i++) u[i] = __shfl_sync(0xffffffffu, val, i);

    float j[4], e[4];
    float mx = -1e30f;
#pragma unroll
    for (int q = 0; q < 4; q++) {
        int s = q * 32 + lane;
        float t = ps[(size_t)b * NCFG + s];
#pragma unroll
        for (int i = 0; i < NE; i++) t += u[i * 2 + ((s >> (6 - i)) & 1)];
        j[q] = t;
        mx = fmaxf(mx, t);
    }
#pragma unroll
    for (int o = 16; o; o >>= 1) mx = fmaxf(mx, __shfl_xor_sync(0xffffffffu, mx, o));

    float p1[NE], p0[NE];
#pragma unroll
    for (int i = 0; i < NE; i++) { p1[i] = 0.f; p0[i] = 0.f; }
#pragma unroll
    for (int q = 0; q < 4; q++) {
        int s = q * 32 + lane;
        e[q] = __expf(j[q] - mx);
#pragma unroll
        for (int i = 0; i < NE; i++) {
            if ((s >> (6 - i)) & 1) p1[i] += e[q];
            else p0[i] += e[q];
        }
    }
#pragma unroll
    for (int o = 16; o; o >>= 1)
#pragma unroll
        for (int i = 0; i < NE; i++) {
            p1[i] += __shfl_xor_sync(0xffffffffu, p1[i], o);
            p0[i] += __shfl_xor_sync(0xffffffffu, p0[i], o);
        }

    float lt = __logf(p1[0] + p0[0]);
#pragma unroll
    for (int q = 0; q < 4; q++)
        out_joint[nb * NCFG + q * 32 + lane] = j[q] - mx - lt;
    if (lane < NE)
        out_marg[nb * NE + lane] = __logf(p1[lane]) - __logf(p0[lane]);
}

// ---------------- launch -------------------------------------------------------
extern "C" void kernel_launch(void* const* d_in, const int* in_sizes, int n_in,
                              void* d_out, int out_size)
{
    const float* input = (const float*)d_in[0];
    const float* ctx   = (const float*)d_in[1];
    const float* W0 = (const float*)d_in[4];
    const float* b0 = (const float*)d_in[5];
    const float* W1 = (const float*)d_in[6];
    const float* b1 = (const float*)d_in[7];
    const float* W2 = (const float*)d_in[8];
    const float* b2 = (const float*)d_in[9];
    const float* R0 = (const float*)d_in[10];
    const float* r0 = (const float*)d_in[11];
    const float* R1 = (const float*)d_in[12];
    const float* r1 = (const float*)d_in[13];

    float* out = (float*)d_out;
    float* out_marg = out;
    float* out_joint = out + (size_t)M_ROWS;

    __nv_bfloat16 *w0p, *w1p, *h1p;
    float *un, *psum;
    cudaGetSymbolAddress((void**)&w0p, g_w0p);
    cudaGetSymbolAddress((void**)&w1p, g_w1p);
    cudaGetSymbolAddress((void**)&h1p, g_h1p);
    cudaGetSymbolAddress((void**)&un, g_un);
    cudaGetSymbolAddress((void**)&psum, g_pairsum);

    cudaFuncSetAttribute(gemm_tc<DIN, 0>, cudaFuncAttributeMaxDynamicSharedMemorySize, SMEM_SZ);
    cudaFuncSetAttribute(gemm_tc<DHv, 1>, cudaFuncAttributeMaxDynamicSharedMemorySize, SMEM_SZ);

    pack_weights<<<DIN, 256>>>(W0, w0p, DIN);
    pack_weights<<<DHv, 256>>>(W1, w1p, DHv);
    cudaMemsetAsync(un, 0, (size_t)M_ROWS * 2 * sizeof(float));

    gemm_tc<DIN, 0><<<dim3(2, M_ROWS / 128), 256, SMEM_SZ>>>(
        input, nullptr, w0p, b0, nullptr, h1p, nullptr);
    gemm_tc<DHv, 1><<<dim3(2, M_ROWS / 128), 256, SMEM_SZ>>>(
        nullptr, h1p, w1p, b1, W2, nullptr, un);
    binary_kernel<<<BSZv, 128>>>(ctx, R0, r0, R1, r1, psum);
    joint_kernel<<<(NN * BSZv) / 8, 256>>>(un, psum, b2, out_marg, out_joint);
}